// round 1
// baseline (speedup 1.0000x reference)
#include <cuda_runtime.h>
#include <math.h>

#define NB 2
#define L 196
#define D 768
#define LD (L*D)
#define MW 7          // 196 bits -> 7 u32 words per row
#define NLTOT (NB*L)  // 392

// ---------------- scratch (static device globals; no runtime alloc) -------
__device__ float    g_V  [NB*LD];
__device__ float    g_Xr [NB*LD];
__device__ float    g_Xi [NB*LD];
__device__ float    g_sty[NB*LD];
__device__ float    g_B1 [NB*LD];
__device__ float    g_B2 [NB*LD];
__device__ float    g_B3 [NB*LD];
__device__ float    g_S  [NB*LD];
__device__ unsigned g_M  [NB*L*MW];

// ---------------- helpers -------------------------------------------------
__device__ __forceinline__ float blockSum256(float v, float* red) {
    #pragma unroll
    for (int o = 16; o; o >>= 1) v += __shfl_xor_sync(0xffffffffu, v, o);
    if ((threadIdx.x & 31) == 0) red[threadIdx.x >> 5] = v;
    __syncthreads();
    if (threadIdx.x < 32) {
        float x = (threadIdx.x < 8) ? red[threadIdx.x] : 0.f;
        #pragma unroll
        for (int o = 4; o; o >>= 1) x += __shfl_xor_sync(0xffffffffu, x, o);
        if (threadIdx.x == 0) red[0] = x;
    }
    __syncthreads();
    float r = red[0];
    __syncthreads();
    return r;
}

// ---------------- K1: patchify + center + L2-normalize --------------------
// V[a,l,:] = (patch - mean) / ||patch - mean||   (var scaling cancels in cosine)
__global__ void k_patch(const float* __restrict__ imgs) {
    __shared__ float red[8];
    int blk = blockIdx.x, a = blk / L, l = blk % L;
    int hh = l / 14, ww = l % 14;
    int tid = threadIdx.x;
    float v[3];
    #pragma unroll
    for (int t = 0; t < 3; t++) {
        int d = tid + t * 256;
        int c = d % 3, pq = d / 3, q = pq & 15, p = pq >> 4;
        v[t] = imgs[((size_t)(a * 3 + c) * 224 + (hh * 16 + p)) * 224 + (ww * 16 + q)];
    }
    float mean = blockSum256(v[0] + v[1] + v[2], red) * (1.f / 768.f);
    float u[3]; float ss = 0.f;
    #pragma unroll
    for (int t = 0; t < 3; t++) { u[t] = v[t] - mean; ss += u[t] * u[t]; }
    float tot = blockSum256(ss, red);
    float inv = 1.f / sqrtf(tot);
    float* out = g_V + (size_t)blk * D;
    #pragma unroll
    for (int t = 0; t < 3; t++) out[tid + t * 256] = u[t] * inv;
}

// ---------------- K2a: zero bitmask (scratch persists across replays) ------
__global__ void k_zeroM() {
    int t = blockIdx.x * 256 + threadIdx.x;
    if (t < NB * L * MW) g_M[t] = 0u;
}

// ---------------- K2b: Sim = V V^T, M0 = triu(Sim > 0.3) as bits ----------
__global__ void k_sim() {
    __shared__ float As[16][17], Bs[16][17];
    int a = blockIdx.z;
    int i0 = blockIdx.y * 16, j0 = blockIdx.x * 16;
    int tx = threadIdx.x, ty = threadIdx.y;
    int i = i0 + ty, j = j0 + tx;
    const float* Vb = g_V + (size_t)a * LD;
    float acc = 0.f;
    for (int k0 = 0; k0 < D; k0 += 16) {
        As[ty][tx] = (i0 + ty < L) ? Vb[(i0 + ty) * D + k0 + tx] : 0.f;
        Bs[ty][tx] = (j0 + ty < L) ? Vb[(j0 + ty) * D + k0 + tx] : 0.f;
        __syncthreads();
        #pragma unroll
        for (int kk = 0; kk < 16; kk++) acc += As[ty][kk] * Bs[tx][kk];
        __syncthreads();
    }
    if (i < L && j < L && j >= i && acc > 0.3f)
        atomicOr(&g_M[(a * L + i) * MW + (j >> 5)], 1u << (j & 31));
}

// ---------------- K3: sequential propagation with global done-check -------
// for i: if M.sum()==N*L stop; else rows j>i: M[j] &= ~M[i]
__global__ void k_prop() {
    __shared__ unsigned m[NB * L * MW];
    __shared__ int sS, sRem, ired[8];
    int tid = threadIdx.x;
    int local = 0;
    for (int t = tid; t < NB * L * MW; t += 256) {
        unsigned w = g_M[t]; m[t] = w; local += __popc(w);
    }
    #pragma unroll
    for (int o = 16; o; o >>= 1) local += __shfl_xor_sync(0xffffffffu, local, o);
    if ((tid & 31) == 0) ired[tid >> 5] = local;
    __syncthreads();
    if (tid == 0) {
        int s = 0;
        #pragma unroll
        for (int w = 0; w < 8; w++) s += ired[w];
        sS = s;
    }
    __syncthreads();

    for (int i = 0; i < L - 1; i++) {
        if (sS == NB * L) break;           // done check (uniform: post-barrier)
        if (tid == 0) sRem = 0;
        __syncthreads();
        int rem = 0;
        int nj = L - 1 - i;
        int cnt = NB * nj * MW;
        for (int t = tid; t < cnt; t += 256) {
            int w = t % MW; int r = t / MW;
            int j = i + 1 + (r % nj); int a = r / nj;
            unsigned rw  = m[(a * L + i) * MW + w];
            unsigned old = m[(a * L + j) * MW + w];
            unsigned drop = old & rw;
            if (drop) {
                m[(a * L + j) * MW + w] = old & ~rw;
                rem += __popc(drop);
            }
        }
        #pragma unroll
        for (int o = 16; o; o >>= 1) rem += __shfl_xor_sync(0xffffffffu, rem, o);
        if ((tid & 31) == 0 && rem) atomicAdd(&sRem, rem);
        __syncthreads();
        if (tid == 0) sS -= sRem;
        __syncthreads();
    }
    for (int t = tid; t < NB * L * MW; t += 256) g_M[t] = m[t];
}

// ---------------- K4: forward DFT (Hermitian half + mirror) ----------------
__global__ void k_dft(const float* __restrict__ x) {
    __shared__ float  xs[D];
    __shared__ float2 tw[D];
    int blk = blockIdx.x, a = blk / L, i = blk % L;
    int tid = threadIdx.x;
    const float* xp = x + ((size_t)a * 197 + 1 + i) * D;
    for (int d = tid; d < D; d += 256) {
        xs[d] = xp[d];
        float sn, cs;
        sincospif((float)d * (1.f / 384.f), &sn, &cs);   // angle 2*pi*d/768
        tw[d] = make_float2(cs, sn);
    }
    __syncthreads();
    size_t base = (size_t)blk * D;
    #pragma unroll
    for (int slot = 0; slot < 2; slot++) {
        int k = tid + slot * 256;
        if (k > 384) continue;
        float ar = 0.f, ai = 0.f;
        int idx = 0;
        #pragma unroll 4
        for (int d = 0; d < D; d++) {
            float xv = xs[d];
            float2 t = tw[idx];
            ar += xv * t.x;
            ai -= xv * t.y;
            idx += k; if (idx >= D) idx -= D;
        }
        g_Xr[base + k] = ar; g_Xi[base + k] = ai;
        float mg = sqrtf(ar * ar + ai * ai);
        g_sty[base + k] = mg;
        if (k >= 1 && k <= 383) {          // Hermitian mirror (bit-exact)
            g_Xr[base + D - k] = ar;
            g_Xi[base + D - k] = -ai;
            g_sty[base + D - k] = mg;
        }
    }
}

// ---------------- K5: per-row cluster stats via bit iteration -------------
// B1 = mask*std, B2 = mask*avg, B3 = mask;  two-pass std matches reference
__global__ void k_stats() {
    __shared__ unsigned mw[MW];
    int blk = blockIdx.x, a = blk / L, i = blk % L;
    int tid = threadIdx.x;
    if (tid < MW) mw[tid] = g_M[(a * L + i) * MW + tid];
    __syncthreads();
    int num = 0;
    #pragma unroll
    for (int w = 0; w < MW; w++) num += __popc(mw[w]);
    float numc = (num > 0) ? (float)num : 1e-7f;

    const float* sb = g_sty + (size_t)a * LD;
    float S1a = 0.f, S1b = 0.f, S1c = 0.f;
    for (int w = 0; w < MW; w++) {
        unsigned bits = mw[w];
        while (bits) {
            int j = (w << 5) + __ffs((int)bits) - 1; bits &= bits - 1;
            const float* sp = sb + (size_t)j * D;
            S1a += sp[tid]; S1b += sp[tid + 256]; S1c += sp[tid + 512];
        }
    }
    float avga = S1a / numc, avgb = S1b / numc, avgc = S1c / numc;
    float S2a = 0.f, S2b = 0.f, S2c = 0.f;
    for (int w = 0; w < MW; w++) {
        unsigned bits = mw[w];
        while (bits) {
            int j = (w << 5) + __ffs((int)bits) - 1; bits &= bits - 1;
            const float* sp = sb + (size_t)j * D;
            float xa = sp[tid]       - avga; S2a += xa * xa;
            float xb = sp[tid + 256] - avgb; S2b += xb * xb;
            float xc = sp[tid + 512] - avgc; S2c += xc * xc;
        }
    }
    size_t off = (size_t)blk * D;
    float sta = sqrtf(S2a / numc), stb = sqrtf(S2b / numc), stc = sqrtf(S2c / numc);
    float ma = (S1a > 0.f) ? 1.f : 0.f;
    float mb = (S1b > 0.f) ? 1.f : 0.f;
    float mc = (S1c > 0.f) ? 1.f : 0.f;
    g_B1[off + tid]       = ma * sta; g_B2[off + tid]       = ma * avga; g_B3[off + tid]       = ma;
    g_B1[off + tid + 256] = mb * stb; g_B2[off + tid + 256] = mb * avgb; g_B3[off + tid + 256] = mb;
    g_B1[off + tid + 512] = mc * stc; g_B2[off + tid + 512] = mc * avgc; g_B3[off + tid + 512] = mc;
}

// ---------------- K6: fused triple GEMM ------------------------------------
// S = (A1@B1 + A2@B2) / max(A2@B3, 1e-7);  A1 = ls*noise, A2 = ls
__global__ void k_gemm(const float* __restrict__ ls, const float* __restrict__ noise) {
    __shared__ float A1s[16][16], A2s[16][16];
    __shared__ float B1s[16][16], B2s[16][16], B3s[16][16];
    int a = blockIdx.z;
    int i0 = blockIdx.y * 16, d0 = blockIdx.x * 16;
    int tx = threadIdx.x, ty = threadIdx.y;
    int i = i0 + ty, d = d0 + tx;
    const float* lsb = ls    + (size_t)a * L * L;
    const float* nsb = noise + (size_t)a * L * L;
    float acc1 = 0.f, acc2 = 0.f, acc3 = 0.f;
    for (int j0 = 0; j0 < L; j0 += 16) {
        int j = j0 + tx;
        float lv = 0.f, nv = 0.f;
        if (i < L && j < L) { lv = lsb[i * L + j]; nv = nsb[i * L + j]; }
        A1s[ty][tx] = lv * nv; A2s[ty][tx] = lv;
        int jr = j0 + ty;
        float b1 = 0.f, b2 = 0.f, b3 = 0.f;
        if (jr < L) {
            size_t o = ((size_t)a * L + jr) * D + d;
            b1 = g_B1[o]; b2 = g_B2[o]; b3 = g_B3[o];
        }
        B1s[ty][tx] = b1; B2s[ty][tx] = b2; B3s[ty][tx] = b3;
        __syncthreads();
        #pragma unroll
        for (int kk = 0; kk < 16; kk++) {
            float a1 = A1s[ty][kk], a2 = A2s[ty][kk];
            acc1 += a1 * B1s[kk][tx];
            acc2 += a2 * B2s[kk][tx];
            acc3 += a2 * B3s[kk][tx];
        }
        __syncthreads();
    }
    if (i < L) g_S[((size_t)a * L + i) * D + d] = (acc1 + acc2) / fmaxf(acc3, 1e-7f);
}

// ---------------- K7: inverse DFT (Hermitian) -------------------------------
// Y[k] = X[k] * S[k]/|X[k]|  (or S[k] if |X|==0, matching angle(0)=0)
__global__ void k_idft(float* __restrict__ out) {
    __shared__ float  Yr[D], Yi[D];
    __shared__ float2 tw[D];
    int blk = blockIdx.x, a = blk / L, i = blk % L;
    int tid = threadIdx.x;
    size_t base = (size_t)blk * D;
    for (int k = tid; k < D; k += 256) {
        float s  = g_S[base + k];
        float xr = g_Xr[base + k], xi = g_Xi[base + k];
        float m2 = xr * xr + xi * xi;
        float yr, yi;
        if (m2 > 0.f) { float r = s / sqrtf(m2); yr = xr * r; yi = xi * r; }
        else          { yr = s; yi = 0.f; }
        Yr[k] = yr; Yi[k] = yi;
        float sn, cs;
        sincospif((float)k * (1.f / 384.f), &sn, &cs);
        tw[k] = make_float2(cs, sn);
    }
    __syncthreads();
    float* op = out + ((size_t)a * 197 + 1 + i) * D;
    #pragma unroll
    for (int slot = 0; slot < 3; slot++) {
        int d = tid + slot * 256;
        float acc = Yr[0] + ((d & 1) ? -Yr[384] : Yr[384]);
        float acc2 = 0.f;
        int idx = d;                       // (1*d) % 768
        #pragma unroll 4
        for (int k = 1; k <= 383; k++) {
            float2 t = tw[idx];
            acc2 += Yr[k] * t.x - Yi[k] * t.y;
            idx += d; if (idx >= D) idx -= D;
        }
        op[d] = (acc + 2.f * acc2) * (1.f / 768.f);
    }
}

// ---------------- K8: copy cls token row ------------------------------------
__global__ void k_cls(const float* __restrict__ x, float* __restrict__ out) {
    int t = blockIdx.x * 256 + threadIdx.x;
    if (t < NB * D) {
        int a = t / D, d = t % D;
        out[(size_t)a * 197 * D + d] = x[(size_t)a * 197 * D + d];
    }
}

// ---------------- launch ----------------------------------------------------
extern "C" void kernel_launch(void* const* d_in, const int* in_sizes, int n_in,
                              void* d_out, int out_size) {
    const float* x     = (const float*)d_in[0];
    const float* imgs  = (const float*)d_in[1];
    const float* ls    = (const float*)d_in[2];
    const float* noise = (const float*)d_in[3];
    float* out = (float*)d_out;

    k_patch<<<NLTOT, 256>>>(imgs);
    k_zeroM<<<(NB * L * MW + 255) / 256, 256>>>();
    k_sim<<<dim3(13, 13, NB), dim3(16, 16)>>>();
    k_prop<<<1, 256>>>();
    k_dft<<<NLTOT, 256>>>(x);
    k_stats<<<NLTOT, 256>>>();
    k_gemm<<<dim3(48, 13, NB), dim3(16, 16)>>>(ls, noise);
    k_idft<<<NLTOT, 256>>>(out);
    k_cls<<<(NB * D + 255) / 256, 256>>>(x, out);
}

// round 2
// speedup vs baseline: 1.6749x; 1.6749x over previous
#include <cuda_runtime.h>
#include <math.h>

#define NB 2
#define L 196
#define D 768
#define LD (L*D)
#define MW 7
#define NLTOT (NB*L)   // 392
#define STRH 448       // padded half-spectrum stride (385 -> 448)
#define NF 832         // fwd table cols (770 -> 13*64)
#define KI 784         // idft K (770 -> 49*16)

// ---------------- scratch ---------------------------------------------------
__device__ float    g_V  [NB*LD];
__device__ float    g_Tf [D*NF];        // fwd twiddles  [d][2k]=cos, [2k+1]=-sin
__device__ float    g_Ti [KI*D];        // idft twiddles [k][d]=cos ; [385+k][d]=-sin ; pad 0
__device__ float    g_YA [NLTOT*KI];    // idft A matrix [row][Yr'(385) | Yi'(385) | 0 pad]
__device__ float    g_Xr [NLTOT*STRH];
__device__ float    g_Xi [NLTOT*STRH];
__device__ float    g_sty[NLTOT*STRH];
__device__ float    g_S  [NLTOT*STRH];
__device__ float    g_B1 [NLTOT*STRH];
__device__ float    g_B2 [NLTOT*STRH];
__device__ float    g_B3 [NLTOT*STRH];
__device__ unsigned g_M  [NB*L*MW];

// ---------------- f32x2 helpers ---------------------------------------------
typedef unsigned long long u64;
__device__ __forceinline__ void fma2(u64 &acc, u64 a, u64 b) {
    asm("fma.rn.f32x2 %0, %1, %2, %0;" : "+l"(acc) : "l"(a), "l"(b));
}
__device__ __forceinline__ u64 pack2(float x, float y) {
    u64 r; asm("mov.b64 %0, {%1, %2};" : "=l"(r) : "f"(x), "f"(y)); return r;
}
__device__ __forceinline__ float2 unpack2(u64 v) {
    float2 f; asm("mov.b64 {%0, %1}, %2;" : "=f"(f.x), "=f"(f.y) : "l"(v)); return f;
}

__device__ __forceinline__ float blockSum256(float v, float* red) {
    #pragma unroll
    for (int o = 16; o; o >>= 1) v += __shfl_xor_sync(0xffffffffu, v, o);
    if ((threadIdx.x & 31) == 0) red[threadIdx.x >> 5] = v;
    __syncthreads();
    if (threadIdx.x < 32) {
        float x = (threadIdx.x < 8) ? red[threadIdx.x] : 0.f;
        #pragma unroll
        for (int o = 4; o; o >>= 1) x += __shfl_xor_sync(0xffffffffu, x, o);
        if (threadIdx.x == 0) red[0] = x;
    }
    __syncthreads();
    float r = red[0];
    __syncthreads();
    return r;
}

// ---------------- K0: twiddle tables ----------------------------------------
__global__ void k_twiddle() {
    __shared__ float2 tw[D];
    int tid = threadIdx.x;
    for (int i = tid; i < D; i += 256) {
        float s, c; sincospif((float)i * (1.f / 384.f), &s, &c);
        tw[i] = make_float2(c, s);
    }
    __syncthreads();
    int r0 = blockIdx.x * 8;
    #pragma unroll
    for (int rr = 0; rr < 8; rr++) {
        int r = r0 + rr;
        if (r >= D + KI) break;
        if (r < D) {                   // Tf row d
            int d = r;
            for (int k = tid; k < NF / 2; k += 256) {
                int idx = (d * k) % D;
                float2 t = tw[idx];
                *reinterpret_cast<float2*>(&g_Tf[(size_t)d * NF + 2 * k]) =
                    make_float2(t.x, -t.y);
            }
        } else {                       // Ti row q
            int q = r - D;
            for (int d = tid; d < D; d += 256) {
                float v;
                if (q < 385)      v =  tw[(q * d) % D].x;
                else if (q < 770) v = -tw[((q - 385) * d) % D].y;
                else              v = 0.f;
                g_Ti[(size_t)q * D + d] = v;
            }
        }
    }
}

// ---------------- K1: patchify + center + L2-normalize ----------------------
__global__ void k_patch(const float* __restrict__ imgs) {
    __shared__ float red[8];
    int blk = blockIdx.x, a = blk / L, l = blk % L;
    int hh = l / 14, ww = l % 14;
    int tid = threadIdx.x;
    float v[3];
    #pragma unroll
    for (int t = 0; t < 3; t++) {
        int d = tid + t * 256;
        int c = d % 3, pq = d / 3, q = pq & 15, p = pq >> 4;
        v[t] = imgs[((size_t)(a * 3 + c) * 224 + (hh * 16 + p)) * 224 + (ww * 16 + q)];
    }
    float mean = blockSum256(v[0] + v[1] + v[2], red) * (1.f / 768.f);
    float u[3]; float ss = 0.f;
    #pragma unroll
    for (int t = 0; t < 3; t++) { u[t] = v[t] - mean; ss += u[t] * u[t]; }
    float tot = blockSum256(ss, red);
    float inv = 1.f / sqrtf(tot);
    float* out = g_V + (size_t)blk * D;
    #pragma unroll
    for (int t = 0; t < 3; t++) out[tid + t * 256] = u[t] * inv;
}

// ---------------- K2a ---------------------------------------------------------
__global__ void k_zeroM() {
    int t = blockIdx.x * 256 + threadIdx.x;
    if (t < NB * L * MW) g_M[t] = 0u;
}

// ---------------- K2b: Sim = V V^T (upper triangle only) --------------------
__global__ void k_sim() {
    int i0 = blockIdx.y * 16, j0 = blockIdx.x * 16;
    if (j0 + 15 < i0) return;          // strictly lower-tri block: no work
    __shared__ float As[16][17], Bs[16][17];
    int a = blockIdx.z;
    int tx = threadIdx.x, ty = threadIdx.y;
    int i = i0 + ty, j = j0 + tx;
    const float* Vb = g_V + (size_t)a * LD;
    float acc = 0.f;
    for (int k0 = 0; k0 < D; k0 += 16) {
        As[ty][tx] = (i0 + ty < L) ? Vb[(i0 + ty) * D + k0 + tx] : 0.f;
        Bs[ty][tx] = (j0 + ty < L) ? Vb[(j0 + ty) * D + k0 + tx] : 0.f;
        __syncthreads();
        #pragma unroll
        for (int kk = 0; kk < 16; kk++) acc += As[ty][kk] * Bs[tx][kk];
        __syncthreads();
    }
    if (i < L && j < L && j >= i && acc > 0.3f)
        atomicOr(&g_M[(a * L + i) * MW + (j >> 5)], 1u << (j & 31));
}

// ---------------- K3: sequential propagation --------------------------------
__global__ void k_prop() {
    __shared__ unsigned m[NB * L * MW];
    __shared__ int sS, sRem, ired[8];
    int tid = threadIdx.x;
    int local = 0;
    for (int t = tid; t < NB * L * MW; t += 256) {
        unsigned w = g_M[t]; m[t] = w; local += __popc(w);
    }
    #pragma unroll
    for (int o = 16; o; o >>= 1) local += __shfl_xor_sync(0xffffffffu, local, o);
    if ((tid & 31) == 0) ired[tid >> 5] = local;
    __syncthreads();
    if (tid == 0) {
        int s = 0;
        #pragma unroll
        for (int w = 0; w < 8; w++) s += ired[w];
        sS = s;
    }
    __syncthreads();
    for (int i = 0; i < L - 1; i++) {
        if (sS == NB * L) break;
        if (tid == 0) sRem = 0;
        __syncthreads();
        int rem = 0;
        int nj = L - 1 - i;
        int cnt = NB * nj * MW;
        for (int t = tid; t < cnt; t += 256) {
            int w = t % MW; int r = t / MW;
            int j = i + 1 + (r % nj); int a = r / nj;
            unsigned rw  = m[(a * L + i) * MW + w];
            unsigned old = m[(a * L + j) * MW + w];
            unsigned drop = old & rw;
            if (drop) { m[(a * L + j) * MW + w] = old & ~rw; rem += __popc(drop); }
        }
        #pragma unroll
        for (int o = 16; o; o >>= 1) rem += __shfl_xor_sync(0xffffffffu, rem, o);
        if ((tid & 31) == 0 && rem) atomicAdd(&sRem, rem);
        __syncthreads();
        if (tid == 0) sS -= sRem;
        __syncthreads();
    }
    for (int t = tid; t < NB * L * MW; t += 256) g_M[t] = m[t];
}

// ---------------- K4: forward DFT as GEMM  C[392,770] = x @ Tf --------------
__global__ void k_fwd(const float* __restrict__ x) {
    __shared__ float As[16][64];
    __shared__ float Bs[16][64];
    int tid = threadIdx.x;
    int tx = tid & 15, ty = tid >> 4;
    int n0 = blockIdx.x * 64, m0 = blockIdx.y * 64;
    u64 acc[4][2];
    #pragma unroll
    for (int i = 0; i < 4; i++) { acc[i][0] = 0ULL; acc[i][1] = 0ULL; }

    int lm = tid >> 2, lk = (tid & 3) << 2;     // A loader
    int bk = tid >> 4, bn4 = (tid & 15) << 2;   // B loader
    int arow = m0 + lm;
    const float* Abase = nullptr;
    bool avalid = arow < NLTOT;
    if (avalid) {
        int a = arow / L, i = arow % L;
        Abase = x + ((size_t)(a * 197 + 1 + i)) * D;
    }
    for (int k0 = 0; k0 < D; k0 += 16) {
        float4 av = make_float4(0.f, 0.f, 0.f, 0.f);
        if (avalid) av = *reinterpret_cast<const float4*>(Abase + k0 + lk);
        As[lk + 0][lm] = av.x; As[lk + 1][lm] = av.y;
        As[lk + 2][lm] = av.z; As[lk + 3][lm] = av.w;
        *reinterpret_cast<float4*>(&Bs[bk][bn4]) =
            *reinterpret_cast<const float4*>(&g_Tf[(size_t)(k0 + bk) * NF + n0 + bn4]);
        __syncthreads();
        #pragma unroll
        for (int kk = 0; kk < 16; kk++) {
            float4 a4 = *reinterpret_cast<float4*>(&As[kk][ty << 2]);
            u64 b01 = *reinterpret_cast<u64*>(&Bs[kk][tx << 2]);
            u64 b23 = *reinterpret_cast<u64*>(&Bs[kk][(tx << 2) + 2]);
            const float* ap = reinterpret_cast<const float*>(&a4);
            #pragma unroll
            for (int im = 0; im < 4; im++) {
                u64 aa = pack2(ap[im], ap[im]);
                fma2(acc[im][0], aa, b01);
                fma2(acc[im][1], aa, b23);
            }
        }
        __syncthreads();
    }
    int n = n0 + (tx << 2);
    int k = n >> 1;
    #pragma unroll
    for (int im = 0; im < 4; im++) {
        int row = m0 + (ty << 2) + im;
        if (row >= NLTOT) continue;
        size_t b = (size_t)row * STRH;
        float2 c01 = unpack2(acc[im][0]);
        float2 c23 = unpack2(acc[im][1]);
        if (k <= 384) {
            g_Xr[b + k] = c01.x; g_Xi[b + k] = c01.y;
            g_sty[b + k] = sqrtf(c01.x * c01.x + c01.y * c01.y);
        }
        if (k + 1 <= 384) {
            g_Xr[b + k + 1] = c23.x; g_Xi[b + k + 1] = c23.y;
            g_sty[b + k + 1] = sqrtf(c23.x * c23.x + c23.y * c23.y);
        }
        // acc per row differ; recompute pairs per im only (acc indexed by im) -- done
    }
}

// ---------------- K5: cluster stats (half spectrum) -------------------------
__global__ void k_stats() {
    __shared__ unsigned mw[MW];
    int blk = blockIdx.x, a = blk / L, i = blk % L;
    int tid = threadIdx.x;
    if (tid < MW) mw[tid] = g_M[(a * L + i) * MW + tid];
    __syncthreads();
    int num = 0;
    #pragma unroll
    for (int w = 0; w < MW; w++) num += __popc(mw[w]);
    float numc = (num > 0) ? (float)num : 1e-7f;
    bool has2 = tid < 129;           // col2 = tid+256 < 385
    int c1 = tid, c2 = tid + 256;

    float S1a = 0.f, S1b = 0.f;
    for (int w = 0; w < MW; w++) {
        unsigned bits = mw[w];
        while (bits) {
            int j = (w << 5) + __ffs((int)bits) - 1; bits &= bits - 1;
            const float* sp = g_sty + (size_t)(a * L + j) * STRH;
            S1a += sp[c1];
            if (has2) S1b += sp[c2];
        }
    }
    float avga = S1a / numc, avgb = S1b / numc;
    float S2a = 0.f, S2b = 0.f;
    for (int w = 0; w < MW; w++) {
        unsigned bits = mw[w];
        while (bits) {
            int j = (w << 5) + __ffs((int)bits) - 1; bits &= bits - 1;
            const float* sp = g_sty + (size_t)(a * L + j) * STRH;
            float xa = sp[c1] - avga; S2a += xa * xa;
            if (has2) { float xb = sp[c2] - avgb; S2b += xb * xb; }
        }
    }
    size_t off = (size_t)blk * STRH;
    float sta = sqrtf(S2a / numc);
    float ma = (S1a > 0.f) ? 1.f : 0.f;
    g_B1[off + c1] = ma * sta; g_B2[off + c1] = ma * avga; g_B3[off + c1] = ma;
    if (has2) {
        float stb = sqrtf(S2b / numc);
        float mb = (S1b > 0.f) ? 1.f : 0.f;
        g_B1[off + c2] = mb * stb; g_B2[off + c2] = mb * avgb; g_B3[off + c2] = mb;
    } else if (tid < 192) {          // zero pad cols [385,448)
        g_B1[off + c2] = 0.f; g_B2[off + c2] = 0.f; g_B3[off + c2] = 0.f;
    }
}

// ---------------- K6: fused triple GEMM (half spectrum) ---------------------
// S[i,d] = (sum_j A1 B1 + A2 B2) / max(A2@B3, 1e-7);  A1=ls*noise, A2=ls
__global__ void k_gemm3(const float* __restrict__ ls, const float* __restrict__ noise) {
    __shared__ float A1s[16][64], A2s[16][64];
    __shared__ float B1s[16][64], B2s[16][64], B3s[16][64];
    int tid = threadIdx.x;
    int tx = tid & 15, ty = tid >> 4;
    int n0 = blockIdx.x * 64, m0 = blockIdx.y * 64;
    int a = blockIdx.z;
    u64 ac1[4][2], ac2[4][2], ac3[4][2];
    #pragma unroll
    for (int i = 0; i < 4; i++) {
        ac1[i][0] = ac1[i][1] = 0ULL;
        ac2[i][0] = ac2[i][1] = 0ULL;
        ac3[i][0] = ac3[i][1] = 0ULL;
    }
    int lm = tid >> 2, lk = (tid & 3) << 2;
    int bk = tid >> 4, bn4 = (tid & 15) << 2;
    const float* lsb = ls    + (size_t)a * L * L;
    const float* nsb = noise + (size_t)a * L * L;

    for (int k0 = 0; k0 < 208; k0 += 16) {
        int ia = m0 + lm, ja = k0 + lk;
        float4 lv = make_float4(0.f, 0.f, 0.f, 0.f), nv = lv;
        if (ia < L && ja < L) {
            lv = *reinterpret_cast<const float4*>(lsb + (size_t)ia * L + ja);
            nv = *reinterpret_cast<const float4*>(nsb + (size_t)ia * L + ja);
        }
        A1s[lk + 0][lm] = lv.x * nv.x; A2s[lk + 0][lm] = lv.x;
        A1s[lk + 1][lm] = lv.y * nv.y; A2s[lk + 1][lm] = lv.y;
        A1s[lk + 2][lm] = lv.z * nv.z; A2s[lk + 2][lm] = lv.z;
        A1s[lk + 3][lm] = lv.w * nv.w; A2s[lk + 3][lm] = lv.w;
        int jb = k0 + bk;
        float4 b1 = make_float4(0.f, 0.f, 0.f, 0.f), b2 = b1, b3 = b1;
        if (jb < L) {
            size_t o = (size_t)(a * L + jb) * STRH + n0 + bn4;
            b1 = *reinterpret_cast<const float4*>(&g_B1[o]);
            b2 = *reinterpret_cast<const float4*>(&g_B2[o]);
            b3 = *reinterpret_cast<const float4*>(&g_B3[o]);
        }
        *reinterpret_cast<float4*>(&B1s[bk][bn4]) = b1;
        *reinterpret_cast<float4*>(&B2s[bk][bn4]) = b2;
        *reinterpret_cast<float4*>(&B3s[bk][bn4]) = b3;
        __syncthreads();
        #pragma unroll
        for (int kk = 0; kk < 16; kk++) {
            float4 a1 = *reinterpret_cast<float4*>(&A1s[kk][ty << 2]);
            float4 a2 = *reinterpret_cast<float4*>(&A2s[kk][ty << 2]);
            u64 b1a = *reinterpret_cast<u64*>(&B1s[kk][tx << 2]);
            u64 b1b = *reinterpret_cast<u64*>(&B1s[kk][(tx << 2) + 2]);
            u64 b2a = *reinterpret_cast<u64*>(&B2s[kk][tx << 2]);
            u64 b2b = *reinterpret_cast<u64*>(&B2s[kk][(tx << 2) + 2]);
            u64 b3a = *reinterpret_cast<u64*>(&B3s[kk][tx << 2]);
            u64 b3b = *reinterpret_cast<u64*>(&B3s[kk][(tx << 2) + 2]);
            const float* a1p = reinterpret_cast<const float*>(&a1);
            const float* a2p = reinterpret_cast<const float*>(&a2);
            #pragma unroll
            for (int im = 0; im < 4; im++) {
                u64 aa1 = pack2(a1p[im], a1p[im]);
                u64 aa2 = pack2(a2p[im], a2p[im]);
                fma2(ac1[im][0], aa1, b1a); fma2(ac1[im][1], aa1, b1b);
                fma2(ac2[im][0], aa2, b2a); fma2(ac2[im][1], aa2, b2b);
                fma2(ac3[im][0], aa2, b3a); fma2(ac3[im][1], aa2, b3b);
            }
        }
        __syncthreads();
    }
    #pragma unroll
    for (int im = 0; im < 4; im++) {
        int i = m0 + (ty << 2) + im;
        if (i >= L) continue;
        size_t ob = (size_t)(a * L + i) * STRH;
        int n = n0 + (tx << 2);
        float2 p1a = unpack2(ac1[im][0]), p1b = unpack2(ac1[im][1]);
        float2 p2a = unpack2(ac2[im][0]), p2b = unpack2(ac2[im][1]);
        float2 p3a = unpack2(ac3[im][0]), p3b = unpack2(ac3[im][1]);
        float num[4] = {p1a.x + p2a.x, p1a.y + p2a.y, p1b.x + p2b.x, p1b.y + p2b.y};
        float den[4] = {p3a.x, p3a.y, p3b.x, p3b.y};
        #pragma unroll
        for (int c = 0; c < 4; c++)
            if (n + c < 385) g_S[ob + n + c] = num[c] / fmaxf(den[c], 1e-7f);
    }
}

// ---------------- K7: build weighted Y for inverse --------------------------
__global__ void k_build_y() {
    int row = blockIdx.x, tid = threadIdx.x;
    size_t bh = (size_t)row * STRH, by = (size_t)row * KI;
    for (int c = tid; c < KI; c += 256) {
        if (c < 385) {
            float s = g_S[bh + c];
            float xr = g_Xr[bh + c], xi = g_Xi[bh + c];
            float m2 = xr * xr + xi * xi;
            float yr, yi;
            if (m2 > 0.f) { float r = s / sqrtf(m2); yr = xr * r; yi = xi * r; }
            else          { yr = s; yi = 0.f; }
            float w = (c == 0 || c == 384) ? 1.f : 2.f;
            g_YA[by + c] = w * yr;
            g_YA[by + 385 + c] = w * yi;
        } else if (c >= 770) {
            g_YA[by + c] = 0.f;
        }
    }
}

// ---------------- K8: inverse DFT as GEMM  out = YA @ Ti / 768 --------------
__global__ void k_idft(float* __restrict__ out) {
    __shared__ float As[16][64];
    __shared__ float Bs[16][64];
    int tid = threadIdx.x;
    int tx = tid & 15, ty = tid >> 4;
    int n0 = blockIdx.x * 64, m0 = blockIdx.y * 64;
    u64 acc[4][2];
    #pragma unroll
    for (int i = 0; i < 4; i++) { acc[i][0] = 0ULL; acc[i][1] = 0ULL; }
    int lm = tid >> 2, lk = (tid & 3) << 2;
    int bk = tid >> 4, bn4 = (tid & 15) << 2;
    int arow = m0 + lm;
    bool avalid = arow < NLTOT;
    const float* Abase = g_YA + (size_t)arow * KI;
    for (int k0 = 0; k0 < KI; k0 += 16) {
        float4 av = make_float4(0.f, 0.f, 0.f, 0.f);
        if (avalid) av = *reinterpret_cast<const float4*>(Abase + k0 + lk);
        As[lk + 0][lm] = av.x; As[lk + 1][lm] = av.y;
        As[lk + 2][lm] = av.z; As[lk + 3][lm] = av.w;
        *reinterpret_cast<float4*>(&Bs[bk][bn4]) =
            *reinterpret_cast<const float4*>(&g_Ti[(size_t)(k0 + bk) * D + n0 + bn4]);
        __syncthreads();
        #pragma unroll
        for (int kk = 0; kk < 16; kk++) {
            float4 a4 = *reinterpret_cast<float4*>(&As[kk][ty << 2]);
            u64 b01 = *reinterpret_cast<u64*>(&Bs[kk][tx << 2]);
            u64 b23 = *reinterpret_cast<u64*>(&Bs[kk][(tx << 2) + 2]);
            const float* ap = reinterpret_cast<const float*>(&a4);
            #pragma unroll
            for (int im = 0; im < 4; im++) {
                u64 aa = pack2(ap[im], ap[im]);
                fma2(acc[im][0], aa, b01);
                fma2(acc[im][1], aa, b23);
            }
        }
        __syncthreads();
    }
    #pragma unroll
    for (int im = 0; im < 4; im++) {
        int row = m0 + (ty << 2) + im;
        if (row >= NLTOT) continue;
        int a = row / L, i = row % L;
        float2 c01 = unpack2(acc[im][0]);
        float2 c23 = unpack2(acc[im][1]);
        float4 o = make_float4(c01.x * (1.f / 768.f), c01.y * (1.f / 768.f),
                               c23.x * (1.f / 768.f), c23.y * (1.f / 768.f));
        *reinterpret_cast<float4*>(
            &out[((size_t)(a * 197 + 1 + i)) * D + n0 + (tx << 2)]) = o;
    }
}

// ---------------- K9: cls row ------------------------------------------------
__global__ void k_cls(const float* __restrict__ x, float* __restrict__ out) {
    int t = blockIdx.x * 256 + threadIdx.x;
    if (t < NB * D) {
        int a = t / D, d = t % D;
        out[(size_t)a * 197 * D + d] = x[(size_t)a * 197 * D + d];
    }
}

// ---------------- launch ------------------------------------------------------
extern "C" void kernel_launch(void* const* d_in, const int* in_sizes, int n_in,
                              void* d_out, int out_size) {
    const float* x     = (const float*)d_in[0];
    const float* imgs  = (const float*)d_in[1];
    const float* ls    = (const float*)d_in[2];
    const float* noise = (const float*)d_in[3];
    float* out = (float*)d_out;

    k_twiddle<<<(D + KI + 7) / 8, 256>>>();
    k_patch<<<NLTOT, 256>>>(imgs);
    k_zeroM<<<(NB * L * MW + 255) / 256, 256>>>();
    k_sim<<<dim3(13, 13, NB), dim3(16, 16)>>>();
    k_prop<<<1, 256>>>();
    k_fwd<<<dim3(13, 7), 256>>>(x);
    k_stats<<<NLTOT, 256>>>();
    k_gemm3<<<dim3(7, 4, NB), 256>>>(ls, noise);
    k_build_y<<<NLTOT, 256>>>();
    k_idft<<<dim3(12, 7), 256>>>(out);
    k_cls<<<(NB * D + 255) / 256, 256>>>(x, out);
}